// round 2
// baseline (speedup 1.0000x reference)
#include <cuda_runtime.h>
#include <math.h>

#define Hn 64
#define Tn 30
#define Ln 100
#define DTC 0.03f
#define NB 128          // blocks
#define NT 256          // threads per block
#define RPB 128         // batch rows per block

#define WBUF_F 19456
#define STRIDE_H 68
#define STRIDE_Z 108
#define SM_FLOATS (WBUF_F + RPB*STRIDE_H*2 + RPB*STRIDE_Z)
#define SMEM_BYTES (SM_FLOATS*4)

#define N_REC  (16384*120)
#define OFF_EXP 1966080
#define OFF_MU  3932160
#define OFF_LV  5570560

// -------- persistent scratch (prepped folded/packed weights) --------
__device__ __align__(16) float g_wpack_e[64*64*4];
__device__ __align__(16) float g_wfp_e[64*4*4];
__device__ __align__(16) float g_bfp_e[64*4];
__device__ __align__(16) float g_wpack_d[64*64*4];
__device__ __align__(16) float g_wfp_d[64*4*4];
__device__ __align__(16) float g_bfp_d[64*4];

__device__ __forceinline__ float sigf(float x){ return 1.0f/(1.0f+__expf(-x)); }
__device__ __forceinline__ float tanhfast(float x){
    x = fminf(fmaxf(x, -15.0f), 15.0f);
    float e = __expf(2.0f*x);
    return (e - 1.0f) / (e + 1.0f);
}
__device__ __forceinline__ float leaky(float x){ return x >= 0.0f ? x : 0.01f*x; }

__device__ __forceinline__ void cpw(float* dst, const float* src, int n){
    for (int i = threadIdx.x*4; i < n; i += NT*4)
        *(float4*)(dst+i) = *(const float4*)(src+i);
}

// -------- prep: fold input path (W_ih@W_se), pack W_hh as [unit][k][gate] --------
__global__ void prep_kernel(const float* __restrict__ W_se, const float* __restrict__ b_se,
    const float* __restrict__ W_ih_e, const float* __restrict__ W_hh_e,
    const float* __restrict__ b_ih_e, const float* __restrict__ b_hh_e,
    const float* __restrict__ W_ih_d, const float* __restrict__ W_hh_d,
    const float* __restrict__ b_ih_d, const float* __restrict__ b_hh_d)
{
    int idx = blockIdx.x*blockDim.x + threadIdx.x;
    if (idx < 16384) {
        int j = idx >> 8, k = (idx >> 2) & 63, q = idx & 3;
        g_wpack_e[idx] = W_hh_e[(q*64+j)*64 + k];
        g_wpack_d[idx] = W_hh_d[(q*64+j)*64 + k];
    }
    if (idx < 1024) {
        int j = idx >> 4, m = (idx >> 2) & 3, q = idx & 3;
        int g = q*64 + j;
        float se = 0.f, sd = 0.f;
        for (int e = 0; e < 64; ++e) {
            se += W_ih_e[g*64+e] * W_se[e*4+m];
            sd += W_ih_d[g*64+e] * W_se[e*4+m];
        }
        g_wfp_e[idx] = se; g_wfp_d[idx] = sd;
    }
    if (idx < 256) {
        int j = idx >> 2, q = idx & 3, g = q*64 + j;
        float se = 0.f, sd = 0.f;
        for (int e = 0; e < 64; ++e) {
            se += W_ih_e[g*64+e] * b_se[e];
            sd += W_ih_d[g*64+e] * b_se[e];
        }
        g_bfp_e[idx] = se + b_ih_e[g] + b_hh_e[g];
        g_bfp_d[idx] = sd + b_ih_d[g] + b_hh_d[g];
    }
}

__global__ void copy_kernel(const float4* __restrict__ src, float4* __restrict__ dst, int n4){
    for (int i = blockIdx.x*blockDim.x + threadIdx.x; i < n4; i += gridDim.x*blockDim.x)
        dst[i] = src[i];
}

// one LSTM step for this thread's 32 units (u0..u0+31); weights broadcast from smem
__device__ __forceinline__ void lstm_half(const float* __restrict__ wb, const float (&h)[64],
                                          float* __restrict__ crow, float* __restrict__ hrow,
                                          float i0, float i1, float i2, float i3, int u0)
{
    const float4* wfp = (const float4*)(wb + 16384);
    const float4* bfp = (const float4*)(wb + 17408);
    #pragma unroll 1
    for (int j = u0; j < u0+32; ++j) {
        const float4* wj = (const float4*)(wb + j*256);
        float4 b  = bfp[j];
        float4 f0 = wfp[j*4+0], f1 = wfp[j*4+1], f2 = wfp[j*4+2], f3 = wfp[j*4+3];
        float ai = b.x + i0*f0.x + i1*f1.x + i2*f2.x + i3*f3.x;
        float af = b.y + i0*f0.y + i1*f1.y + i2*f2.y + i3*f3.y;
        float ag = b.z + i0*f0.z + i1*f1.z + i2*f2.z + i3*f3.z;
        float ao = b.w + i0*f0.w + i1*f1.w + i2*f2.w + i3*f3.w;
        #pragma unroll
        for (int k = 0; k < 64; ++k) {
            float4 w = wj[k];
            ai = fmaf(h[k], w.x, ai);
            af = fmaf(h[k], w.y, af);
            ag = fmaf(h[k], w.z, ag);
            ao = fmaf(h[k], w.w, ao);
        }
        float c = crow[j];
        c = sigf(af)*c + sigf(ai)*tanhfast(ag);
        float hn = sigf(ao)*tanhfast(c);
        crow[j] = c;
        hrow[j] = hn;
    }
}

// 3 hidden layers + final (100 outs split 50/50); optionally fuse the z-sample
__device__ __forceinline__ void mlp_forward(const float* __restrict__ wb, float (&h)[64],
                                            float* __restrict__ hrow, int u0, int uh,
                                            float* __restrict__ zrow, float* __restrict__ gout,
                                            bool is_lv, const float* __restrict__ epsrow)
{
    const float* Ws = wb;
    const float* Wf = wb + 12288;
    const float* bs = wb + 18688;
    const float* bf = wb + 18880;
    #pragma unroll 1
    for (int l = 0; l < 3; ++l) {
        #pragma unroll 1
        for (int j = u0; j < u0+32; ++j) {
            float acc = bs[l*64 + j];
            const float4* wj = (const float4*)(Ws + l*4096 + j*64);
            #pragma unroll
            for (int k = 0; k < 64; k += 4) {
                float4 w = wj[k>>2];
                acc = fmaf(h[k],w.x, fmaf(h[k+1],w.y, fmaf(h[k+2],w.z, fmaf(h[k+3],w.w, acc))));
            }
            hrow[j] = leaky(acc);
        }
        __syncthreads();
        #pragma unroll
        for (int k = 0; k < 64; ++k) h[k] = hrow[k];
        __syncthreads();
    }
    #pragma unroll 1
    for (int j = uh*50; j < uh*50+50; ++j) {
        float acc = bf[j];
        const float4* wj = (const float4*)(Wf + j*64);
        #pragma unroll
        for (int k = 0; k < 64; k += 4) {
            float4 w = wj[k>>2];
            acc = fmaf(h[k],w.x, fmaf(h[k+1],w.y, fmaf(h[k+2],w.z, fmaf(h[k+3],w.w, acc))));
        }
        float v = leaky(acc);
        gout[j] = v;
        if (!is_lv) {
            zrow[j] = v;                                   // stash mu
        } else {
            float e = epsrow[j];
            zrow[j] = tanhfast(fmaf(e, __expf(0.5f*v), zrow[j]));  // z
        }
    }
}

__global__ void __launch_bounds__(NT, 1) vae_kernel(
    const float* __restrict__ expert, const float* __restrict__ init_state, const float* __restrict__ eps,
    const float* __restrict__ mean_Ws, const float* __restrict__ mean_bs,
    const float* __restrict__ mean_Wf, const float* __restrict__ mean_bf,
    const float* __restrict__ lv_Ws, const float* __restrict__ lv_bs,
    const float* __restrict__ lv_Wf, const float* __restrict__ lv_bf,
    const float* __restrict__ W_init, const float* __restrict__ b_init,
    const float* __restrict__ W_c, const float* __restrict__ b_c,
    float* __restrict__ out)
{
    extern __shared__ float sm[];
    float* wbuf   = sm;
    float* hstage = sm + WBUF_F;
    float* cbuf   = hstage + RPB*STRIDE_H;
    float* zbuf   = cbuf + RPB*STRIDE_H;

    const int tid = threadIdx.x;
    const int r   = tid & 127;
    const int uh  = tid >> 7;        // 0/1: which half of the 64 units this thread owns
    const int u0  = uh * 32;
    const int row = blockIdx.x * RPB + r;

    // ---------------- encoder ----------------
    cpw(wbuf,        g_wpack_e, 16384);
    cpw(wbuf+16384,  g_wfp_e,   1024);
    cpw(wbuf+17408,  g_bfp_e,   256);
    __syncthreads();

    float h[64];
    #pragma unroll
    for (int k = 0; k < 64; ++k) h[k] = 0.0f;
    for (int j = u0; j < u0+32; ++j) cbuf[r*STRIDE_H + j] = 0.0f;

    float px = 0.f, py = 0.f;
    const float4* trow = (const float4*)(expert + (size_t)row * (Tn*4));

    #pragma unroll 1
    for (int t = 0; t < Tn; ++t) {
        float4 a = trow[t];
        float i0 = (t == 0) ? a.x : a.x - px;
        float i1 = (t == 0) ? a.y : a.y - py;
        px = a.x; py = a.y;
        lstm_half(wbuf, h, cbuf + r*STRIDE_H, hstage + r*STRIDE_H, i0, i1, a.z, a.w, u0);
        __syncthreads();
        #pragma unroll
        for (int k = 0; k < 64; k += 4) {
            float4 v = *(const float4*)&hstage[r*STRIDE_H + k];
            h[k] = v.x; h[k+1] = v.y; h[k+2] = v.z; h[k+3] = v.w;
        }
        __syncthreads();
    }

    // save hT (cbuf's encoder c is dead)
    if (uh == 0) {
        #pragma unroll
        for (int k = 0; k < 64; ++k) cbuf[r*STRIDE_H + k] = h[k];
    }
    __syncthreads();

    // ---------------- mean MLP ----------------
    cpw(wbuf,        mean_Ws, 12288);
    cpw(wbuf+12288,  mean_Wf, 6400);
    cpw(wbuf+18688,  mean_bs, 192);
    cpw(wbuf+18880,  mean_bf, 100);
    __syncthreads();
    mlp_forward(wbuf, h, hstage + r*STRIDE_H, u0, uh,
                zbuf + r*STRIDE_Z, out + OFF_MU + (size_t)row*100, false, nullptr);
    __syncthreads();

    // ---------------- log_var MLP + sample z ----------------
    #pragma unroll
    for (int k = 0; k < 64; ++k) h[k] = cbuf[r*STRIDE_H + k];   // restore hT
    cpw(wbuf,        lv_Ws, 12288);
    cpw(wbuf+12288,  lv_Wf, 6400);
    cpw(wbuf+18688,  lv_bs, 192);
    cpw(wbuf+18880,  lv_bf, 100);
    __syncthreads();
    mlp_forward(wbuf, h, hstage + r*STRIDE_H, u0, uh,
                zbuf + r*STRIDE_Z, out + OFF_LV + (size_t)row*100, true, eps + (size_t)row*100);
    __syncthreads();

    // ---------------- dh = z @ W_init^T + b_init ----------------
    cpw(wbuf,       W_init, 6400);
    cpw(wbuf+6400,  b_init, 64);
    __syncthreads();
    {
        const float4* zr = (const float4*)(zbuf + r*STRIDE_Z);
        #pragma unroll 1
        for (int j = u0; j < u0+32; ++j) {
            float acc = wbuf[6400 + j];
            const float4* wj = (const float4*)(wbuf + j*100);
            #pragma unroll
            for (int k = 0; k < 100; k += 4) {
                float4 w = wj[k>>2]; float4 z = zr[k>>2];
                acc = fmaf(z.x,w.x, fmaf(z.y,w.y, fmaf(z.z,w.z, fmaf(z.w,w.w, acc))));
            }
            hstage[r*STRIDE_H + j] = acc;
            cbuf[r*STRIDE_H + j]   = acc;   // c0 = dh
        }
    }
    __syncthreads();
    #pragma unroll
    for (int k = 0; k < 64; ++k) h[k] = hstage[r*STRIDE_H + k];
    __syncthreads();

    // ---------------- decoder ----------------
    cpw(wbuf,        g_wpack_d, 16384);
    cpw(wbuf+16384,  g_wfp_d,   1024);
    cpw(wbuf+17408,  g_bfp_d,   256);
    cpw(wbuf+17664,  W_c,       128);
    if (tid == 0) { wbuf[17792] = b_c[0]; wbuf[17793] = b_c[1]; }
    __syncthreads();

    float4 prev = ((const float4*)init_state)[row];
    float* pb   = wbuf + 18432;                  // per-row prev broadcast
    float* rec  = out + (size_t)row * (Tn*4);

    #pragma unroll 1
    for (int t = 0; t < Tn; ++t) {
        lstm_half(wbuf, h, cbuf + r*STRIDE_H, hstage + r*STRIDE_H,
                  prev.x, prev.y, prev.z, prev.w, u0);
        __syncthreads();
        #pragma unroll
        for (int k = 0; k < 64; k += 4) {
            float4 v = *(const float4*)&hstage[r*STRIDE_H + k];
            h[k] = v.x; h[k+1] = v.y; h[k+2] = v.z; h[k+3] = v.w;
        }
        if (uh == 0) {
            float a0 = wbuf[17792], a1 = wbuf[17793];
            const float4* wc0 = (const float4*)(wbuf + 17664);
            const float4* wc1 = (const float4*)(wbuf + 17664 + 64);
            #pragma unroll
            for (int k = 0; k < 64; k += 4) {
                float4 w0 = wc0[k>>2], w1 = wc1[k>>2];
                a0 = fmaf(h[k],w0.x, fmaf(h[k+1],w0.y, fmaf(h[k+2],w0.z, fmaf(h[k+3],w0.w, a0))));
                a1 = fmaf(h[k],w1.x, fmaf(h[k+1],w1.y, fmaf(h[k+2],w1.z, fmaf(h[k+3],w1.w, a1))));
            }
            float pedal = a0;
            float steer = fminf(fmaxf(a1, -0.5f), 0.5f);
            float x = prev.x, y = prev.y, psi = prev.z, v = prev.w;
            float v1 = fminf(fmaxf(fmaf(pedal, DTC, v), 0.0f), 30.0f);
            float pd = fminf(fmaxf(v * __tanf(steer) * (1.0f/2.5f), -1.57f), 1.57f);
            float s, c; __sincosf(psi, &s, &c);
            float4 cur = make_float4(fmaf(v*c, DTC, x), fmaf(v*s, DTC, y), fmaf(pd, DTC, psi), v1);
            *(float4*)(rec + t*4) = cur;
            *(float4*)(pb + r*4)  = cur;
            prev = cur;
        }
        __syncthreads();
        if (uh == 1) prev = *(const float4*)(pb + r*4);
    }
}

extern "C" void kernel_launch(void* const* d_in, const int* in_sizes, int n_in,
                              void* d_out, int out_size)
{
    const float* expert     = (const float*)d_in[0];
    const float* init_state = (const float*)d_in[1];
    const float* eps        = (const float*)d_in[2];
    const float* W_se       = (const float*)d_in[3];
    const float* b_se       = (const float*)d_in[4];
    const float* W_ih_e     = (const float*)d_in[5];
    const float* W_hh_e     = (const float*)d_in[6];
    const float* b_ih_e     = (const float*)d_in[7];
    const float* b_hh_e     = (const float*)d_in[8];
    const float* mean_Ws    = (const float*)d_in[9];
    const float* mean_bs    = (const float*)d_in[10];
    const float* mean_Wf    = (const float*)d_in[11];
    const float* mean_bf    = (const float*)d_in[12];
    const float* lv_Ws      = (const float*)d_in[13];
    const float* lv_bs      = (const float*)d_in[14];
    const float* lv_Wf      = (const float*)d_in[15];
    const float* lv_bf      = (const float*)d_in[16];
    const float* W_init     = (const float*)d_in[17];
    const float* b_init     = (const float*)d_in[18];
    const float* W_ih_d     = (const float*)d_in[19];
    const float* W_hh_d     = (const float*)d_in[20];
    const float* b_ih_d     = (const float*)d_in[21];
    const float* b_hh_d     = (const float*)d_in[22];
    const float* W_c        = (const float*)d_in[23];
    const float* b_c        = (const float*)d_in[24];
    float* out = (float*)d_out;

    cudaFuncSetAttribute(vae_kernel, cudaFuncAttributeMaxDynamicSharedMemorySize, SMEM_BYTES);

    prep_kernel<<<64, 256>>>(W_se, b_se, W_ih_e, W_hh_e, b_ih_e, b_hh_e,
                             W_ih_d, W_hh_d, b_ih_d, b_hh_d);
    copy_kernel<<<256, 256>>>((const float4*)expert, (float4*)(out + OFF_EXP), N_REC/4);
    vae_kernel<<<NB, NT, SMEM_BYTES>>>(expert, init_state, eps,
        mean_Ws, mean_bs, mean_Wf, mean_bf,
        lv_Ws, lv_bs, lv_Wf, lv_bf,
        W_init, b_init, W_c, b_c, out);
}

// round 3
// speedup vs baseline: 1.0713x; 1.0713x over previous
#include <cuda_runtime.h>
#include <math.h>

#define Hn 64
#define Tn 30
#define Ln 100
#define DTC 0.03f
#define NB 128          // blocks
#define NT 256          // threads per block
#define RPB 128         // batch rows per block

#define WBUF_F 19456
#define STRIDE_H 68
#define STRIDE_Z 108
#define SM_FLOATS (WBUF_F + RPB*STRIDE_H*2 + RPB*STRIDE_Z)
#define SMEM_BYTES (SM_FLOATS*4)

#define N_REC  (16384*120)
#define OFF_EXP 1966080
#define OFF_MU  3932160
#define OFF_LV  5570560

typedef unsigned long long u64;

// -------- persistent scratch (prepped folded/packed weights) --------
__device__ __align__(16) float g_wpack_e[64*64*4];
__device__ __align__(16) float g_wfp_e[64*4*4];
__device__ __align__(16) float g_bfp_e[64*4];
__device__ __align__(16) float g_wpack_d[64*64*4];
__device__ __align__(16) float g_wfp_d[64*4*4];
__device__ __align__(16) float g_bfp_d[64*4];

// ---- packed f32x2 helpers (FFMA2 — ptxas never emits this from C++) ----
__device__ __forceinline__ u64 fma2(u64 a, u64 b, u64 c){
    u64 d;
    asm("fma.rn.f32x2 %0, %1, %2, %3;" : "=l"(d) : "l"(a), "l"(b), "l"(c));
    return d;
}
__device__ __forceinline__ u64 pack2(float lo, float hi){
    u64 d; asm("mov.b64 %0, {%1, %2};" : "=l"(d) : "f"(lo), "f"(hi)); return d;
}
__device__ __forceinline__ void unpack2(u64 a, float& lo, float& hi){
    asm("mov.b64 {%0, %1}, %2;" : "=f"(lo), "=f"(hi) : "l"(a));
}
__device__ __forceinline__ float hsum2(u64 a){
    float lo, hi; unpack2(a, lo, hi); return lo + hi;
}

__device__ __forceinline__ float sigf(float x){ return 1.0f/(1.0f+__expf(-x)); }
__device__ __forceinline__ float tanhfast(float x){
    x = fminf(fmaxf(x, -15.0f), 15.0f);
    float e = __expf(2.0f*x);
    return (e - 1.0f) / (e + 1.0f);
}
__device__ __forceinline__ float leaky(float x){ return x >= 0.0f ? x : 0.01f*x; }

__device__ __forceinline__ void cpw(float* dst, const float* src, int n){
    for (int i = threadIdx.x*4; i < n; i += NT*4)
        *(float4*)(dst+i) = *(const float4*)(src+i);
}

// -------- prep: fold input path (W_ih@W_se), pack W_hh as [j][k/2][gate][2] --------
__global__ void prep_kernel(const float* __restrict__ W_se, const float* __restrict__ b_se,
    const float* __restrict__ W_ih_e, const float* __restrict__ W_hh_e,
    const float* __restrict__ b_ih_e, const float* __restrict__ b_hh_e,
    const float* __restrict__ W_ih_d, const float* __restrict__ W_hh_d,
    const float* __restrict__ b_ih_d, const float* __restrict__ b_hh_d)
{
    int idx = blockIdx.x*blockDim.x + threadIdx.x;
    if (idx < 16384) {
        int j = idx >> 8, rr = idx & 255;
        int p = rr >> 3, g = (rr >> 1) & 3, d = rr & 1;
        int src = (g*64 + j)*64 + 2*p + d;
        g_wpack_e[idx] = W_hh_e[src];
        g_wpack_d[idx] = W_hh_d[src];
    }
    if (idx < 1024) {
        int j = idx >> 4, m = (idx >> 2) & 3, q = idx & 3;
        int g = q*64 + j;
        float se = 0.f, sd = 0.f;
        for (int e = 0; e < 64; ++e) {
            se += W_ih_e[g*64+e] * W_se[e*4+m];
            sd += W_ih_d[g*64+e] * W_se[e*4+m];
        }
        g_wfp_e[idx] = se; g_wfp_d[idx] = sd;
    }
    if (idx < 256) {
        int j = idx >> 2, q = idx & 3, g = q*64 + j;
        float se = 0.f, sd = 0.f;
        for (int e = 0; e < 64; ++e) {
            se += W_ih_e[g*64+e] * b_se[e];
            sd += W_ih_d[g*64+e] * b_se[e];
        }
        g_bfp_e[idx] = se + b_ih_e[g] + b_hh_e[g];
        g_bfp_d[idx] = sd + b_ih_d[g] + b_hh_d[g];
    }
}

__global__ void copy_kernel(const float4* __restrict__ src, float4* __restrict__ dst, int n4){
    for (int i = blockIdx.x*blockDim.x + threadIdx.x; i < n4; i += gridDim.x*blockDim.x)
        dst[i] = src[i];
}

// one LSTM step for this thread's 32 units; FFMA2 over k-pairs, weights broadcast from smem
__device__ __forceinline__ void lstm_half(const float* __restrict__ wb, const u64 (&h2)[32],
                                          float* __restrict__ crow, float* __restrict__ hrow,
                                          u64 im0, u64 im1, u64 im2, u64 im3, int u0)
{
    const ulonglong2* wfp = (const ulonglong2*)(wb + 16384); // [j*4+m]: .x={w_i,w_f} .y={w_g,w_o}
    const ulonglong2* bfp = (const ulonglong2*)(wb + 17408); // [j]:     .x={b_i,b_f} .y={b_g,b_o}
    #pragma unroll 1
    for (int j = u0; j < u0+32; ++j) {
        ulonglong2 bj = bfp[j];
        u64 AIF = bj.x, AGO = bj.y;
        const ulonglong2* wm = wfp + j*4;
        AIF = fma2(im0, wm[0].x, AIF); AGO = fma2(im0, wm[0].y, AGO);
        AIF = fma2(im1, wm[1].x, AIF); AGO = fma2(im1, wm[1].y, AGO);
        AIF = fma2(im2, wm[2].x, AIF); AGO = fma2(im2, wm[2].y, AGO);
        AIF = fma2(im3, wm[3].x, AIF); AGO = fma2(im3, wm[3].y, AGO);

        u64 Ai = 0ULL, Af = 0ULL, Ag = 0ULL, Ao = 0ULL;
        const ulonglong2* wj = (const ulonglong2*)(wb + j*256);
        #pragma unroll
        for (int p = 0; p < 32; ++p) {
            ulonglong2 wA = wj[2*p];     // {i-pair, f-pair}
            ulonglong2 wB = wj[2*p+1];   // {g-pair, o-pair}
            Ai = fma2(h2[p], wA.x, Ai);
            Af = fma2(h2[p], wA.y, Af);
            Ag = fma2(h2[p], wB.x, Ag);
            Ao = fma2(h2[p], wB.y, Ao);
        }
        float ii, ff, gg, oo;
        unpack2(AIF, ii, ff); unpack2(AGO, gg, oo);
        float ai = hsum2(Ai) + ii;
        float af = hsum2(Af) + ff;
        float ag = hsum2(Ag) + gg;
        float ao = hsum2(Ao) + oo;
        float c = crow[j];
        c = sigf(af)*c + sigf(ai)*tanhfast(ag);
        float hn = sigf(ao)*tanhfast(c);
        crow[j] = c;
        hrow[j] = hn;
    }
}

// dot of h2 (64 values as 32 pairs) with a 64-float row (16B aligned)
__device__ __forceinline__ float dot64(const u64 (&h2)[32], const float* __restrict__ wrow){
    const ulonglong2* w2 = (const ulonglong2*)wrow;
    u64 A = 0ULL, B = 0ULL;
    #pragma unroll
    for (int i = 0; i < 16; ++i) {
        ulonglong2 w = w2[i];
        A = fma2(h2[2*i],   w.x, A);
        B = fma2(h2[2*i+1], w.y, B);
    }
    return hsum2(A) + hsum2(B);
}

__device__ __forceinline__ void load_h2(u64 (&h2)[32], const float* __restrict__ hrow){
    const ulonglong2* hr = (const ulonglong2*)hrow;
    #pragma unroll
    for (int i = 0; i < 16; ++i) {
        ulonglong2 v = hr[i];
        h2[2*i] = v.x; h2[2*i+1] = v.y;
    }
}

// 3 hidden layers + final (100 outs split 50/50); optionally fuse the z-sample
__device__ __forceinline__ void mlp_forward(const float* __restrict__ wb, u64 (&h2)[32],
                                            float* __restrict__ hrow, int u0, int uh,
                                            float* __restrict__ zrow, float* __restrict__ gout,
                                            bool is_lv, const float* __restrict__ epsrow)
{
    const float* Ws = wb;
    const float* Wf = wb + 12288;
    const float* bs = wb + 18688;
    const float* bf = wb + 18880;
    #pragma unroll 1
    for (int l = 0; l < 3; ++l) {
        #pragma unroll 1
        for (int j = u0; j < u0+32; ++j) {
            float acc = dot64(h2, Ws + l*4096 + j*64) + bs[l*64 + j];
            hrow[j] = leaky(acc);
        }
        __syncthreads();
        load_h2(h2, hrow);
        __syncthreads();
    }
    #pragma unroll 1
    for (int j = uh*50; j < uh*50+50; ++j) {
        float v = leaky(dot64(h2, Wf + j*64) + bf[j]);
        gout[j] = v;
        if (!is_lv) {
            zrow[j] = v;                                   // stash mu
        } else {
            float e = epsrow[j];
            zrow[j] = tanhfast(fmaf(e, __expf(0.5f*v), zrow[j]));  // z
        }
    }
}

__global__ void __launch_bounds__(NT, 1) vae_kernel(
    const float* __restrict__ expert, const float* __restrict__ init_state, const float* __restrict__ eps,
    const float* __restrict__ mean_Ws, const float* __restrict__ mean_bs,
    const float* __restrict__ mean_Wf, const float* __restrict__ mean_bf,
    const float* __restrict__ lv_Ws, const float* __restrict__ lv_bs,
    const float* __restrict__ lv_Wf, const float* __restrict__ lv_bf,
    const float* __restrict__ W_init, const float* __restrict__ b_init,
    const float* __restrict__ W_c, const float* __restrict__ b_c,
    float* __restrict__ out)
{
    extern __shared__ float sm[];
    float* wbuf   = sm;
    float* hstage = sm + WBUF_F;
    float* cbuf   = hstage + RPB*STRIDE_H;
    float* zbuf   = cbuf + RPB*STRIDE_H;

    const int tid = threadIdx.x;
    const int r   = tid & 127;
    const int uh  = tid >> 7;        // 0/1: which half of the 64 units this thread owns
    const int u0  = uh * 32;
    const int row = blockIdx.x * RPB + r;

    // ---------------- encoder ----------------
    cpw(wbuf,        g_wpack_e, 16384);
    cpw(wbuf+16384,  g_wfp_e,   1024);
    cpw(wbuf+17408,  g_bfp_e,   256);
    __syncthreads();

    u64 h2[32];
    #pragma unroll
    for (int i = 0; i < 32; ++i) h2[i] = 0ULL;
    for (int j = u0; j < u0+32; ++j) cbuf[r*STRIDE_H + j] = 0.0f;

    float px = 0.f, py = 0.f;
    const float4* trow = (const float4*)(expert + (size_t)row * (Tn*4));

    #pragma unroll 1
    for (int t = 0; t < Tn; ++t) {
        float4 a = trow[t];
        float i0 = (t == 0) ? a.x : a.x - px;
        float i1 = (t == 0) ? a.y : a.y - py;
        px = a.x; py = a.y;
        lstm_half(wbuf, h2, cbuf + r*STRIDE_H, hstage + r*STRIDE_H,
                  pack2(i0,i0), pack2(i1,i1), pack2(a.z,a.z), pack2(a.w,a.w), u0);
        __syncthreads();
        load_h2(h2, hstage + r*STRIDE_H);
        __syncthreads();
    }

    // save hT into cbuf (encoder c is dead)
    if (uh == 0) {
        ulonglong2* cd = (ulonglong2*)(cbuf + r*STRIDE_H);
        #pragma unroll
        for (int i = 0; i < 16; ++i) cd[i] = make_ulonglong2(h2[2*i], h2[2*i+1]);
    }
    __syncthreads();

    // ---------------- mean MLP ----------------
    cpw(wbuf,        mean_Ws, 12288);
    cpw(wbuf+12288,  mean_Wf, 6400);
    cpw(wbuf+18688,  mean_bs, 192);
    cpw(wbuf+18880,  mean_bf, 100);
    __syncthreads();
    mlp_forward(wbuf, h2, hstage + r*STRIDE_H, u0, uh,
                zbuf + r*STRIDE_Z, out + OFF_MU + (size_t)row*100, false, nullptr);
    __syncthreads();

    // ---------------- log_var MLP + sample z ----------------
    load_h2(h2, cbuf + r*STRIDE_H);   // restore hT
    cpw(wbuf,        lv_Ws, 12288);
    cpw(wbuf+12288,  lv_Wf, 6400);
    cpw(wbuf+18688,  lv_bs, 192);
    cpw(wbuf+18880,  lv_bf, 100);
    __syncthreads();
    mlp_forward(wbuf, h2, hstage + r*STRIDE_H, u0, uh,
                zbuf + r*STRIDE_Z, out + OFF_LV + (size_t)row*100, true, eps + (size_t)row*100);
    __syncthreads();

    // ---------------- dh = z @ W_init^T + b_init ----------------
    cpw(wbuf,       W_init, 6400);
    cpw(wbuf+6400,  b_init, 64);
    __syncthreads();
    {
        const ulonglong2* z2 = (const ulonglong2*)(zbuf + r*STRIDE_Z);
        #pragma unroll 1
        for (int j = u0; j < u0+32; ++j) {
            const ulonglong2* w2 = (const ulonglong2*)(wbuf + j*100);
            u64 A = 0ULL, B = 0ULL;
            #pragma unroll
            for (int i = 0; i < 25; ++i) {
                ulonglong2 w = w2[i];
                ulonglong2 z = z2[i];
                A = fma2(z.x, w.x, A);
                B = fma2(z.y, w.y, B);
            }
            float acc = hsum2(A) + hsum2(B) + wbuf[6400 + j];
            hstage[r*STRIDE_H + j] = acc;
            cbuf[r*STRIDE_H + j]   = acc;   // c0 = dh
        }
    }
    __syncthreads();
    load_h2(h2, hstage + r*STRIDE_H);
    __syncthreads();

    // ---------------- decoder ----------------
    cpw(wbuf,        g_wpack_d, 16384);
    cpw(wbuf+16384,  g_wfp_d,   1024);
    cpw(wbuf+17408,  g_bfp_d,   256);
    cpw(wbuf+17664,  W_c,       128);
    if (tid == 0) { wbuf[17792] = b_c[0]; wbuf[17793] = b_c[1]; }
    __syncthreads();

    float4 prev = ((const float4*)init_state)[row];
    float* pb   = wbuf + 18432;                  // per-row prev broadcast
    float* rec  = out + (size_t)row * (Tn*4);

    #pragma unroll 1
    for (int t = 0; t < Tn; ++t) {
        lstm_half(wbuf, h2, cbuf + r*STRIDE_H, hstage + r*STRIDE_H,
                  pack2(prev.x,prev.x), pack2(prev.y,prev.y),
                  pack2(prev.z,prev.z), pack2(prev.w,prev.w), u0);
        __syncthreads();
        load_h2(h2, hstage + r*STRIDE_H);
        if (uh == 0) {
            float a0 = wbuf[17792] + dot64(h2, wbuf + 17664);
            float a1 = wbuf[17793] + dot64(h2, wbuf + 17664 + 64);
            float pedal = a0;
            float steer = fminf(fmaxf(a1, -0.5f), 0.5f);
            float x = prev.x, y = prev.y, psi = prev.z, v = prev.w;
            float v1 = fminf(fmaxf(fmaf(pedal, DTC, v), 0.0f), 30.0f);
            float pd = fminf(fmaxf(v * __tanf(steer) * (1.0f/2.5f), -1.57f), 1.57f);
            float s, c; __sincosf(psi, &s, &c);
            float4 cur = make_float4(fmaf(v*c, DTC, x), fmaf(v*s, DTC, y), fmaf(pd, DTC, psi), v1);
            *(float4*)(rec + t*4) = cur;
            *(float4*)(pb + r*4)  = cur;
            prev = cur;
        }
        __syncthreads();
        if (uh == 1) prev = *(const float4*)(pb + r*4);
    }
}

extern "C" void kernel_launch(void* const* d_in, const int* in_sizes, int n_in,
                              void* d_out, int out_size)
{
    const float* expert     = (const float*)d_in[0];
    const float* init_state = (const float*)d_in[1];
    const float* eps        = (const float*)d_in[2];
    const float* W_se       = (const float*)d_in[3];
    const float* b_se       = (const float*)d_in[4];
    const float* W_ih_e     = (const float*)d_in[5];
    const float* W_hh_e     = (const float*)d_in[6];
    const float* b_ih_e     = (const float*)d_in[7];
    const float* b_hh_e     = (const float*)d_in[8];
    const float* mean_Ws    = (const float*)d_in[9];
    const float* mean_bs    = (const float*)d_in[10];
    const float* mean_Wf    = (const float*)d_in[11];
    const float* mean_bf    = (const float*)d_in[12];
    const float* lv_Ws      = (const float*)d_in[13];
    const float* lv_bs      = (const float*)d_in[14];
    const float* lv_Wf      = (const float*)d_in[15];
    const float* lv_bf      = (const float*)d_in[16];
    const float* W_init     = (const float*)d_in[17];
    const float* b_init     = (const float*)d_in[18];
    const float* W_ih_d     = (const float*)d_in[19];
    const float* W_hh_d     = (const float*)d_in[20];
    const float* b_ih_d     = (const float*)d_in[21];
    const float* b_hh_d     = (const float*)d_in[22];
    const float* W_c        = (const float*)d_in[23];
    const float* b_c        = (const float*)d_in[24];
    float* out = (float*)d_out;

    cudaFuncSetAttribute(vae_kernel, cudaFuncAttributeMaxDynamicSharedMemorySize, SMEM_BYTES);

    prep_kernel<<<64, 256>>>(W_se, b_se, W_ih_e, W_hh_e, b_ih_e, b_hh_e,
                             W_ih_d, W_hh_d, b_ih_d, b_hh_d);
    copy_kernel<<<256, 256>>>((const float4*)expert, (float4*)(out + OFF_EXP), N_REC/4);
    vae_kernel<<<NB, NT, SMEM_BYTES>>>(expert, init_state, eps,
        mean_Ws, mean_bs, mean_Wf, mean_bf,
        lv_Ws, lv_bs, lv_Wf, lv_bf,
        W_init, b_init, W_c, b_c, out);
}

// round 4
// speedup vs baseline: 1.2290x; 1.1472x over previous
#include <cuda_runtime.h>
#include <math.h>

#define Hn 64
#define Tn 30
#define Ln 100
#define DTC 0.03f
#define NB 128          // blocks
#define NT 512          // threads per block
#define RPB 128         // batch rows per block
#define UPT 16          // units per thread (64/4)

#define WBUF_F 19456
#define STRIDE_H 68
#define STRIDE_Z 108
#define SM_FLOATS (WBUF_F + RPB*STRIDE_H*2 + RPB*STRIDE_Z)
#define SMEM_BYTES (SM_FLOATS*4)

#define N_REC  (16384*120)
#define OFF_EXP 1966080
#define OFF_MU  3932160
#define OFF_LV  5570560

typedef unsigned long long u64;

// -------- persistent scratch (prepped folded/packed weights) --------
__device__ __align__(16) float g_wpack_e[64*64*4];
__device__ __align__(16) float g_wfp_e[64*4*4];
__device__ __align__(16) float g_bfp_e[64*4];
__device__ __align__(16) float g_wpack_d[64*64*4];
__device__ __align__(16) float g_wfp_d[64*4*4];
__device__ __align__(16) float g_bfp_d[64*4];

// ---- packed f32x2 helpers ----
__device__ __forceinline__ u64 fma2(u64 a, u64 b, u64 c){
    u64 d;
    asm("fma.rn.f32x2 %0, %1, %2, %3;" : "=l"(d) : "l"(a), "l"(b), "l"(c));
    return d;
}
__device__ __forceinline__ u64 pack2(float lo, float hi){
    u64 d; asm("mov.b64 %0, {%1, %2};" : "=l"(d) : "f"(lo), "f"(hi)); return d;
}
__device__ __forceinline__ void unpack2(u64 a, float& lo, float& hi){
    asm("mov.b64 {%0, %1}, %2;" : "=f"(lo), "=f"(hi) : "l"(a));
}
__device__ __forceinline__ float hsum2(u64 a){
    float lo, hi; unpack2(a, lo, hi); return lo + hi;
}

__device__ __forceinline__ float sigf(float x){ return 1.0f/(1.0f+__expf(-x)); }
__device__ __forceinline__ float tanhfast(float x){
    x = fminf(fmaxf(x, -15.0f), 15.0f);
    float e = __expf(2.0f*x);
    return (e - 1.0f) / (e + 1.0f);
}
__device__ __forceinline__ float leaky(float x){ return x >= 0.0f ? x : 0.01f*x; }

__device__ __forceinline__ void cpw(float* dst, const float* src, int n){
    for (int i = threadIdx.x*4; i < n; i += NT*4)
        *(float4*)(dst+i) = *(const float4*)(src+i);
}

// -------- prep: fold input path (W_ih@W_se), pack W_hh as [j][k/2][gate][2] --------
__global__ void prep_kernel(const float* __restrict__ W_se, const float* __restrict__ b_se,
    const float* __restrict__ W_ih_e, const float* __restrict__ W_hh_e,
    const float* __restrict__ b_ih_e, const float* __restrict__ b_hh_e,
    const float* __restrict__ W_ih_d, const float* __restrict__ W_hh_d,
    const float* __restrict__ b_ih_d, const float* __restrict__ b_hh_d)
{
    int idx = blockIdx.x*blockDim.x + threadIdx.x;
    if (idx < 16384) {
        int j = idx >> 8, rr = idx & 255;
        int p = rr >> 3, g = (rr >> 1) & 3, d = rr & 1;
        int src = (g*64 + j)*64 + 2*p + d;
        g_wpack_e[idx] = W_hh_e[src];
        g_wpack_d[idx] = W_hh_d[src];
    }
    if (idx < 1024) {
        int j = idx >> 4, m = (idx >> 2) & 3, q = idx & 3;
        int g = q*64 + j;
        float se = 0.f, sd = 0.f;
        for (int e = 0; e < 64; ++e) {
            se += W_ih_e[g*64+e] * W_se[e*4+m];
            sd += W_ih_d[g*64+e] * W_se[e*4+m];
        }
        g_wfp_e[idx] = se; g_wfp_d[idx] = sd;
    }
    if (idx < 256) {
        int j = idx >> 2, q = idx & 3, g = q*64 + j;
        float se = 0.f, sd = 0.f;
        for (int e = 0; e < 64; ++e) {
            se += W_ih_e[g*64+e] * b_se[e];
            sd += W_ih_d[g*64+e] * b_se[e];
        }
        g_bfp_e[idx] = se + b_ih_e[g] + b_hh_e[g];
        g_bfp_d[idx] = sd + b_ih_d[g] + b_hh_d[g];
    }
}

__global__ void copy_kernel(const float4* __restrict__ src, float4* __restrict__ dst, int n4){
    for (int i = blockIdx.x*blockDim.x + threadIdx.x; i < n4; i += gridDim.x*blockDim.x)
        dst[i] = src[i];
}

// one LSTM step for this thread's 16 units; c lives in registers
__device__ __forceinline__ void lstm_q(const float* __restrict__ wb, const u64 (&h2)[32],
                                       float (&cr)[UPT], float* __restrict__ hrow,
                                       u64 im0, u64 im1, u64 im2, u64 im3, int u0)
{
    const ulonglong2* wfp = (const ulonglong2*)(wb + 16384);
    const ulonglong2* bfp = (const ulonglong2*)(wb + 17408);
    #pragma unroll 1
    for (int jj = 0; jj < UPT; ++jj) {
        int j = u0 + jj;
        ulonglong2 bj = bfp[j];
        u64 AIF = bj.x, AGO = bj.y;
        const ulonglong2* wm = wfp + j*4;
        AIF = fma2(im0, wm[0].x, AIF); AGO = fma2(im0, wm[0].y, AGO);
        AIF = fma2(im1, wm[1].x, AIF); AGO = fma2(im1, wm[1].y, AGO);
        AIF = fma2(im2, wm[2].x, AIF); AGO = fma2(im2, wm[2].y, AGO);
        AIF = fma2(im3, wm[3].x, AIF); AGO = fma2(im3, wm[3].y, AGO);

        u64 Ai = 0ULL, Af = 0ULL, Ag = 0ULL, Ao = 0ULL;
        const ulonglong2* wj = (const ulonglong2*)(wb + j*256);
        #pragma unroll
        for (int p = 0; p < 32; ++p) {
            ulonglong2 wA = wj[2*p];     // {i-pair, f-pair}
            ulonglong2 wB = wj[2*p+1];   // {g-pair, o-pair}
            Ai = fma2(h2[p], wA.x, Ai);
            Af = fma2(h2[p], wA.y, Af);
            Ag = fma2(h2[p], wB.x, Ag);
            Ao = fma2(h2[p], wB.y, Ao);
        }
        float ii, ff, gg, oo;
        unpack2(AIF, ii, ff); unpack2(AGO, gg, oo);
        float ai = hsum2(Ai) + ii;
        float af = hsum2(Af) + ff;
        float ag = hsum2(Ag) + gg;
        float ao = hsum2(Ao) + oo;
        float c = cr[jj];
        c = sigf(af)*c + sigf(ai)*tanhfast(ag);
        cr[jj] = c;
        hrow[j] = sigf(ao)*tanhfast(c);
    }
}

__device__ __forceinline__ float dot64(const u64 (&h2)[32], const float* __restrict__ wrow){
    const ulonglong2* w2 = (const ulonglong2*)wrow;
    u64 A = 0ULL, B = 0ULL;
    #pragma unroll
    for (int i = 0; i < 16; ++i) {
        ulonglong2 w = w2[i];
        A = fma2(h2[2*i],   w.x, A);
        B = fma2(h2[2*i+1], w.y, B);
    }
    return hsum2(A) + hsum2(B);
}

__device__ __forceinline__ void load_h2(u64 (&h2)[32], const float* __restrict__ hrow){
    const ulonglong2* hr = (const ulonglong2*)hrow;
    #pragma unroll
    for (int i = 0; i < 16; ++i) {
        ulonglong2 v = hr[i];
        h2[2*i] = v.x; h2[2*i+1] = v.y;
    }
}

// 3 hidden layers + final (100 outs split 25 per quarter)
__device__ __forceinline__ void mlp_forward(const float* __restrict__ wb, u64 (&h2)[32],
                                            float* __restrict__ hrow, int u0, int q,
                                            float* __restrict__ zrow, float* __restrict__ gout,
                                            bool is_lv, const float* __restrict__ epsrow)
{
    const float* Ws = wb;
    const float* Wf = wb + 12288;
    const float* bs = wb + 18688;
    const float* bf = wb + 18880;
    #pragma unroll 1
    for (int l = 0; l < 3; ++l) {
        #pragma unroll 1
        for (int j = u0; j < u0+UPT; ++j)
            hrow[j] = leaky(dot64(h2, Ws + l*4096 + j*64) + bs[l*64 + j]);
        __syncthreads();
        load_h2(h2, hrow);
        __syncthreads();
    }
    #pragma unroll 1
    for (int j = q*25; j < q*25+25; ++j) {
        float v = leaky(dot64(h2, Wf + j*64) + bf[j]);
        gout[j] = v;
        if (!is_lv) {
            zrow[j] = v;                                   // stash mu
        } else {
            float e = epsrow[j];
            zrow[j] = tanhfast(fmaf(e, __expf(0.5f*v), zrow[j]));  // z
        }
    }
}

__global__ void __launch_bounds__(NT, 1) vae_kernel(
    const float* __restrict__ expert, const float* __restrict__ init_state, const float* __restrict__ eps,
    const float* __restrict__ mean_Ws, const float* __restrict__ mean_bs,
    const float* __restrict__ mean_Wf, const float* __restrict__ mean_bf,
    const float* __restrict__ lv_Ws, const float* __restrict__ lv_bs,
    const float* __restrict__ lv_Wf, const float* __restrict__ lv_bf,
    const float* __restrict__ W_init, const float* __restrict__ b_init,
    const float* __restrict__ W_c, const float* __restrict__ b_c,
    float* __restrict__ out)
{
    extern __shared__ float sm[];
    float* wbuf   = sm;
    float* hstage = sm + WBUF_F;
    float* cbuf   = hstage + RPB*STRIDE_H;     // hT stash between MLPs
    float* zbuf   = cbuf + RPB*STRIDE_H;

    const int tid = threadIdx.x;
    const int r   = tid & 127;
    const int q   = tid >> 7;        // 0..3: which quarter of the 64 units
    const int u0  = q * UPT;
    const int row = blockIdx.x * RPB + r;

    // ---------------- encoder ----------------
    cpw(wbuf,        g_wpack_e, 16384);
    cpw(wbuf+16384,  g_wfp_e,   1024);
    cpw(wbuf+17408,  g_bfp_e,   256);
    __syncthreads();

    u64 h2[32];
    #pragma unroll
    for (int i = 0; i < 32; ++i) h2[i] = 0ULL;
    float cr[UPT];
    #pragma unroll
    for (int i = 0; i < UPT; ++i) cr[i] = 0.0f;

    float px = 0.f, py = 0.f;
    const float4* trow = (const float4*)(expert + (size_t)row * (Tn*4));

    #pragma unroll 1
    for (int t = 0; t < Tn; ++t) {
        float4 a = trow[t];
        float i0 = (t == 0) ? a.x : a.x - px;
        float i1 = (t == 0) ? a.y : a.y - py;
        px = a.x; py = a.y;
        lstm_q(wbuf, h2, cr, hstage + r*STRIDE_H,
               pack2(i0,i0), pack2(i1,i1), pack2(a.z,a.z), pack2(a.w,a.w), u0);
        __syncthreads();
        load_h2(h2, hstage + r*STRIDE_H);
        __syncthreads();
    }

    // save hT into cbuf
    if (q == 0) {
        ulonglong2* cd = (ulonglong2*)(cbuf + r*STRIDE_H);
        #pragma unroll
        for (int i = 0; i < 16; ++i) cd[i] = make_ulonglong2(h2[2*i], h2[2*i+1]);
    }
    __syncthreads();

    // ---------------- mean MLP ----------------
    cpw(wbuf,        mean_Ws, 12288);
    cpw(wbuf+12288,  mean_Wf, 6400);
    cpw(wbuf+18688,  mean_bs, 192);
    cpw(wbuf+18880,  mean_bf, 100);
    __syncthreads();
    mlp_forward(wbuf, h2, hstage + r*STRIDE_H, u0, q,
                zbuf + r*STRIDE_Z, out + OFF_MU + (size_t)row*100, false, nullptr);
    __syncthreads();

    // ---------------- log_var MLP + sample z ----------------
    load_h2(h2, cbuf + r*STRIDE_H);   // restore hT
    cpw(wbuf,        lv_Ws, 12288);
    cpw(wbuf+12288,  lv_Wf, 6400);
    cpw(wbuf+18688,  lv_bs, 192);
    cpw(wbuf+18880,  lv_bf, 100);
    __syncthreads();
    mlp_forward(wbuf, h2, hstage + r*STRIDE_H, u0, q,
                zbuf + r*STRIDE_Z, out + OFF_LV + (size_t)row*100, true, eps + (size_t)row*100);
    __syncthreads();

    // ---------------- dh = z @ W_init^T + b_init ----------------
    cpw(wbuf,       W_init, 6400);
    cpw(wbuf+6400,  b_init, 64);
    __syncthreads();
    {
        const ulonglong2* z2 = (const ulonglong2*)(zbuf + r*STRIDE_Z);
        #pragma unroll 1
        for (int jj = 0; jj < UPT; ++jj) {
            int j = u0 + jj;
            const ulonglong2* w2 = (const ulonglong2*)(wbuf + j*100);
            u64 A = 0ULL, B = 0ULL;
            #pragma unroll
            for (int i = 0; i < 25; ++i) {
                ulonglong2 w = w2[i];
                ulonglong2 z = z2[i];
                A = fma2(z.x, w.x, A);
                B = fma2(z.y, w.y, B);
            }
            float acc = hsum2(A) + hsum2(B) + wbuf[6400 + j];
            hstage[r*STRIDE_H + j] = acc;
            cr[jj] = acc;                 // c0 = dh (registers)
        }
    }
    __syncthreads();
    load_h2(h2, hstage + r*STRIDE_H);
    __syncthreads();

    // ---------------- decoder ----------------
    cpw(wbuf,        g_wpack_d, 16384);
    cpw(wbuf+16384,  g_wfp_d,   1024);
    cpw(wbuf+17408,  g_bfp_d,   256);
    cpw(wbuf+17664,  W_c,       128);
    if (tid == 0) { wbuf[17792] = b_c[0]; wbuf[17793] = b_c[1]; }
    __syncthreads();

    float4 prev = ((const float4*)init_state)[row];
    float* pb   = wbuf + 18432;                  // per-row prev broadcast
    float* rec  = out + (size_t)row * (Tn*4);

    #pragma unroll 1
    for (int t = 0; t < Tn; ++t) {
        lstm_q(wbuf, h2, cr, hstage + r*STRIDE_H,
               pack2(prev.x,prev.x), pack2(prev.y,prev.y),
               pack2(prev.z,prev.z), pack2(prev.w,prev.w), u0);
        __syncthreads();
        load_h2(h2, hstage + r*STRIDE_H);
        if (q == 0) {
            float a0 = wbuf[17792] + dot64(h2, wbuf + 17664);
            float a1 = wbuf[17793] + dot64(h2, wbuf + 17664 + 64);
            float pedal = a0;
            float steer = fminf(fmaxf(a1, -0.5f), 0.5f);
            float x = prev.x, y = prev.y, psi = prev.z, v = prev.w;
            float v1 = fminf(fmaxf(fmaf(pedal, DTC, v), 0.0f), 30.0f);
            float pd = fminf(fmaxf(v * __tanf(steer) * (1.0f/2.5f), -1.57f), 1.57f);
            float s, c; __sincosf(psi, &s, &c);
            float4 cur = make_float4(fmaf(v*c, DTC, x), fmaf(v*s, DTC, y), fmaf(pd, DTC, psi), v1);
            *(float4*)(rec + t*4) = cur;
            *(float4*)(pb + r*4)  = cur;
            prev = cur;
        }
        __syncthreads();
        if (q != 0) prev = *(const float4*)(pb + r*4);
    }
}

extern "C" void kernel_launch(void* const* d_in, const int* in_sizes, int n_in,
                              void* d_out, int out_size)
{
    const float* expert     = (const float*)d_in[0];
    const float* init_state = (const float*)d_in[1];
    const float* eps        = (const float*)d_in[2];
    const float* W_se       = (const float*)d_in[3];
    const float* b_se       = (const float*)d_in[4];
    const float* W_ih_e     = (const float*)d_in[5];
    const float* W_hh_e     = (const float*)d_in[6];
    const float* b_ih_e     = (const float*)d_in[7];
    const float* b_hh_e     = (const float*)d_in[8];
    const float* mean_Ws    = (const float*)d_in[9];
    const float* mean_bs    = (const float*)d_in[10];
    const float* mean_Wf    = (const float*)d_in[11];
    const float* mean_bf    = (const float*)d_in[12];
    const float* lv_Ws      = (const float*)d_in[13];
    const float* lv_bs      = (const float*)d_in[14];
    const float* lv_Wf      = (const float*)d_in[15];
    const float* lv_bf      = (const float*)d_in[16];
    const float* W_init     = (const float*)d_in[17];
    const float* b_init     = (const float*)d_in[18];
    const float* W_ih_d     = (const float*)d_in[19];
    const float* W_hh_d     = (const float*)d_in[20];
    const float* b_ih_d     = (const float*)d_in[21];
    const float* b_hh_d     = (const float*)d_in[22];
    const float* W_c        = (const float*)d_in[23];
    const float* b_c        = (const float*)d_in[24];
    float* out = (float*)d_out;

    cudaFuncSetAttribute(vae_kernel, cudaFuncAttributeMaxDynamicSharedMemorySize, SMEM_BYTES);

    prep_kernel<<<64, 256>>>(W_se, b_se, W_ih_e, W_hh_e, b_ih_e, b_hh_e,
                             W_ih_d, W_hh_d, b_ih_d, b_hh_d);
    copy_kernel<<<256, 256>>>((const float4*)expert, (float4*)(out + OFF_EXP), N_REC/4);
    vae_kernel<<<NB, NT, SMEM_BYTES>>>(expert, init_state, eps,
        mean_Ws, mean_bs, mean_Wf, mean_bf,
        lv_Ws, lv_bs, lv_Wf, lv_bf,
        W_init, b_init, W_c, b_c, out);
}

// round 6
// speedup vs baseline: 3.0994x; 2.5220x over previous
#include <cuda_runtime.h>
#include <cuda_bf16.h>
#include <math.h>
#include <cstdint>

#define Tn 30
#define DTC 0.03f
#define NB 128
#define NT 512

// ---- smem layout (float offsets) ----
#define AHI_F   0        // 128 rows x 144B (64 bf16 + pad) = 4608 floats
#define ALO_F   4608
#define BW_F    9216     // B tiles (hi 9216 + lo 9216) / MLP weights (19456)
#define WFB_F   28672    // padded fold+bias: 64 u x 20 floats = 1280
#define WC_F    29952    // W_c 128 + b_c 2 (+pad) = 132
#define PB_F    30084    // per-row input/prev float4 (512)
#define PART_F  30596    // W_c partials (512)
#define HST_F   31108    // 128*68
#define ZB_F    39812    // 128*108
#define SM_FLOATS 53636
#define SMEM_BYTES (SM_FLOATS*4)

#define STRIDE_H 68
#define STRIDE_Z 108
#define AROW_B  144      // bytes per A/B row in smem
#define BHI_B   (BW_F*4)
#define BLO_B   (BW_F*4 + 36864)

#define N_REC  (16384*120)
#define OFF_EXP 1966080
#define OFF_MU  3932160
#define OFF_LV  5570560

typedef unsigned long long u64;

// -------- persistent prepped weights --------
__device__ __align__(16) unsigned short g_Bhi_e[16384];  // bf16 hi of W_hh_e [256][64]
__device__ __align__(16) unsigned short g_Blo_e[16384];
__device__ __align__(16) unsigned short g_Bhi_d[16384];
__device__ __align__(16) unsigned short g_Blo_d[16384];
__device__ __align__(16) float g_wfp_e[1024];   // folded input weights [(u*4+g)*4+m]
__device__ __align__(16) float g_bfp_e[256];    // folded bias [u*4+g]
__device__ __align__(16) float g_wfp_d[1024];
__device__ __align__(16) float g_bfp_d[256];

// ---- PTX helpers ----
__device__ __forceinline__ uint32_t smem_to_u32(const void* p){
    uint32_t a;
    asm("{ .reg .u64 t; cvta.to.shared.u64 t, %1; cvt.u32.u64 %0, t; }" : "=r"(a) : "l"(p));
    return a;
}
__device__ __forceinline__ void ldm4(uint32_t* r, uint32_t addr){
    asm volatile("ldmatrix.sync.aligned.m8n8.x4.shared.b16 {%0,%1,%2,%3}, [%4];"
        : "=r"(r[0]), "=r"(r[1]), "=r"(r[2]), "=r"(r[3]) : "r"(addr));
}
__device__ __forceinline__ void mma_bf16(float* d, const uint32_t* a, uint32_t b0, uint32_t b1){
    asm volatile("mma.sync.aligned.m16n8k16.row.col.f32.bf16.bf16.f32 "
        "{%0,%1,%2,%3}, {%4,%5,%6,%7}, {%8,%9}, {%0,%1,%2,%3};"
        : "+f"(d[0]), "+f"(d[1]), "+f"(d[2]), "+f"(d[3])
        : "r"(a[0]), "r"(a[1]), "r"(a[2]), "r"(a[3]), "r"(b0), "r"(b1));
}

// ---- fma2 helpers (MLP path) ----
__device__ __forceinline__ u64 fma2(u64 a, u64 b, u64 c){
    u64 d; asm("fma.rn.f32x2 %0, %1, %2, %3;" : "=l"(d) : "l"(a), "l"(b), "l"(c)); return d;
}
__device__ __forceinline__ void unpack2(u64 a, float& lo, float& hi){
    asm("mov.b64 {%0, %1}, %2;" : "=f"(lo), "=f"(hi) : "l"(a));
}
__device__ __forceinline__ float hsum2(u64 a){ float lo, hi; unpack2(a, lo, hi); return lo + hi; }

__device__ __forceinline__ float sigf(float x){ return __fdividef(1.0f, 1.0f + __expf(-x)); }
__device__ __forceinline__ float tanhfast(float x){
    x = fminf(fmaxf(x, -15.0f), 15.0f);
    float e = __expf(2.0f*x);
    return __fdividef(e - 1.0f, e + 1.0f);
}
__device__ __forceinline__ float leaky(float x){ return x >= 0.0f ? x : 0.01f*x; }

__device__ __forceinline__ void cpw(float* dst, const float* src, int n){
    for (int i = threadIdx.x*4; i < n; i += NT*4)
        *(float4*)(dst+i) = *(const float4*)(src+i);
}
// copy [256][64] bf16 (128B rows) into padded 144B-stride smem rows
__device__ __forceinline__ void cpB(float* smB, const unsigned short* gB){
    const uint4* src = (const uint4*)gB;
    for (int c = threadIdx.x; c < 2048; c += NT) {
        int n = c >> 3, cc = c & 7;
        *(uint4*)(smB + n*36 + cc*4) = src[c];
    }
}
__device__ __forceinline__ uint32_t pkbf2(float a, float b){
    __nv_bfloat162 t = __floats2bfloat162_rn(a, b);
    return *reinterpret_cast<uint32_t*>(&t);
}

// ================ prep kernel ================
__global__ void prep_kernel(const float* __restrict__ W_se, const float* __restrict__ b_se,
    const float* __restrict__ W_ih_e, const float* __restrict__ W_hh_e,
    const float* __restrict__ b_ih_e, const float* __restrict__ b_hh_e,
    const float* __restrict__ W_ih_d, const float* __restrict__ W_hh_d,
    const float* __restrict__ b_ih_d, const float* __restrict__ b_hh_d)
{
    int idx = blockIdx.x*blockDim.x + threadIdx.x;
    if (idx < 16384) {
        float we = W_hh_e[idx];
        __nv_bfloat16 hb = __float2bfloat16(we);
        g_Bhi_e[idx] = __bfloat16_as_ushort(hb);
        g_Blo_e[idx] = __bfloat16_as_ushort(__float2bfloat16(we - __bfloat162float(hb)));
        float wd = W_hh_d[idx];
        __nv_bfloat16 hd = __float2bfloat16(wd);
        g_Bhi_d[idx] = __bfloat16_as_ushort(hd);
        g_Blo_d[idx] = __bfloat16_as_ushort(__float2bfloat16(wd - __bfloat162float(hd)));
    }
    if (idx < 1024) {
        int u = idx >> 4, g = (idx >> 2) & 3, m = idx & 3;
        int gg = g*64 + u;
        float se = 0.f, sd = 0.f;
        for (int e = 0; e < 64; ++e) {
            se += W_ih_e[gg*64+e] * W_se[e*4+m];
            sd += W_ih_d[gg*64+e] * W_se[e*4+m];
        }
        g_wfp_e[idx] = se; g_wfp_d[idx] = sd;
    }
    if (idx < 256) {
        int u = idx >> 2, g = idx & 3, gg = g*64 + u;
        float se = 0.f, sd = 0.f;
        for (int e = 0; e < 64; ++e) {
            se += W_ih_e[gg*64+e] * b_se[e];
            sd += W_ih_d[gg*64+e] * b_se[e];
        }
        g_bfp_e[idx] = se + b_ih_e[gg] + b_hh_e[gg];
        g_bfp_d[idx] = sd + b_ih_d[gg] + b_hh_d[gg];
    }
}

__global__ void copy_kernel(const float4* __restrict__ src, float4* __restrict__ dst, int n4){
    for (int i = blockIdx.x*blockDim.x + threadIdx.x; i < n4; i += gridDim.x*blockDim.x)
        dst[i] = src[i];
}

// load padded fold+bias into WFB: [u][20] = wf(16) + bias(4)
__device__ __forceinline__ void cpWU(float* dst, const float* wfp, const float* bfp){
    for (int i = threadIdx.x; i < 1280; i += NT) {
        int u = i / 20, j = i % 20;
        dst[i] = (j < 16) ? wfp[u*16 + j] : bfp[u*4 + (j-16)];
    }
}

// ---- MLP helpers (fma2) ----
__device__ __forceinline__ float dot64(const u64 (&h2)[32], const float* __restrict__ wrow){
    const ulonglong2* w2 = (const ulonglong2*)wrow;
    u64 A = 0ULL, B = 0ULL;
    #pragma unroll
    for (int i = 0; i < 16; ++i) {
        ulonglong2 w = w2[i];
        A = fma2(h2[2*i],   w.x, A);
        B = fma2(h2[2*i+1], w.y, B);
    }
    return hsum2(A) + hsum2(B);
}
__device__ __forceinline__ void load_h2(u64 (&h2)[32], const float* __restrict__ hrow){
    const ulonglong2* hr = (const ulonglong2*)hrow;
    #pragma unroll
    for (int i = 0; i < 16; ++i) { ulonglong2 v = hr[i]; h2[2*i] = v.x; h2[2*i+1] = v.y; }
}
__device__ __forceinline__ void mlp_forward(const float* __restrict__ wb, u64 (&h2)[32],
                                            float* __restrict__ hrow, int u0, int q,
                                            float* __restrict__ zrow, float* __restrict__ gout,
                                            bool is_lv, const float* __restrict__ epsrow)
{
    const float* Ws = wb;
    const float* Wf = wb + 12288;
    const float* bs = wb + 18688;
    const float* bf = wb + 18880;
    #pragma unroll 1
    for (int l = 0; l < 3; ++l) {
        #pragma unroll 1
        for (int j = u0; j < u0+16; ++j)
            hrow[j] = leaky(dot64(h2, Ws + l*4096 + j*64) + bs[l*64 + j]);
        __syncthreads();
        load_h2(h2, hrow);
        __syncthreads();
    }
    #pragma unroll 1
    for (int j = q*25; j < q*25+25; ++j) {
        float v = leaky(dot64(h2, Wf + j*64) + bf[j]);
        gout[j] = v;
        if (!is_lv) zrow[j] = v;
        else {
            float e = epsrow[j];
            zrow[j] = tanhfast(fmaf(e, __expf(0.5f*v), zrow[j]));
        }
    }
}

// ================= main kernel =================
__global__ void __launch_bounds__(NT, 1) vae_kernel(
    const float* __restrict__ expert, const float* __restrict__ init_state, const float* __restrict__ eps,
    const float* __restrict__ mean_Ws, const float* __restrict__ mean_bs,
    const float* __restrict__ mean_Wf, const float* __restrict__ mean_bf,
    const float* __restrict__ lv_Ws, const float* __restrict__ lv_bs,
    const float* __restrict__ lv_Wf, const float* __restrict__ lv_bf,
    const float* __restrict__ W_init, const float* __restrict__ b_init,
    const float* __restrict__ W_c, const float* __restrict__ b_c,
    float* __restrict__ out)
{
    extern __shared__ float sm[];
    char* smc = (char*)sm;
    uint32_t smb = smem_to_u32(sm);
    const int tid = threadIdx.x;
    const int wid = tid >> 5, lane = tid & 31;
    const int gid = lane >> 2, tig = lane & 3;
    const int mtile = wid & 7, nhalf = wid >> 3;
    const int r0 = mtile*16 + gid, r1 = r0 + 8;

    // per-lane ldmatrix address components
    const int arow = (lane & 7) + ((lane >> 3) & 1)*8;
    const int ak8  = ((lane >> 4) & 1)*8;
    const int brow = (lane & 7) + ((lane >> 4) & 1)*8;
    const int bk8  = ((lane >> 3) & 1)*8;
    const uint32_t aAddrH = smb + (uint32_t)((mtile*16 + arow)*AROW_B + ak8*2);
    const uint32_t aAddrL = aAddrH + 18432;
    const uint32_t bBaseHi = smb + BHI_B + (uint32_t)((nhalf*32 + brow)*AROW_B + bk8*2);
    const uint32_t bBaseLo = bBaseHi + 36864;

    float4* pb4 = (float4*)(sm + PB_F);
    float* part = sm + PART_F;
    const float4* WU = (const float4*)(sm + WFB_F);

    // ---------------- encoder setup ----------------
    cpB(sm + BW_F,        g_Bhi_e);
    cpB(sm + BW_F + 9216, g_Blo_e);
    cpWU(sm + WFB_F, g_wfp_e, g_bfp_e);
    __syncthreads();

    float cst[16];
    #pragma unroll
    for (int i = 0; i < 16; ++i) cst[i] = 0.0f;
    float px = 0.f, py = 0.f;
    const float4* trow = (tid < 128) ? (const float4*)(expert + (size_t)(blockIdx.x*128 + tid)*(Tn*4)) : nullptr;

    // ---------------- encoder loop ----------------
    #pragma unroll 1
    for (int t = 0; t < Tn; ++t) {
        // (a) input staging
        if (tid < 128) {
            float4 a = trow[t];
            float4 in;
            in.x = (t == 0) ? a.x : a.x - px;
            in.y = (t == 0) ? a.y : a.y - py;
            in.z = a.z; in.w = a.w;
            px = a.x; py = a.y;
            pb4[tid] = in;
        }
        // (b+d) mma
        float acc[16][4];
        #pragma unroll
        for (int i = 0; i < 16; ++i) { acc[i][0]=0.f; acc[i][1]=0.f; acc[i][2]=0.f; acc[i][3]=0.f; }
        if (t > 0) {
            __syncthreads();   // (c)
            #pragma unroll
            for (int kt = 0; kt < 4; ++kt) {
                uint32_t aH[4], aL[4];
                ldm4(aH, aAddrH + kt*32);
                ldm4(aL, aAddrL + kt*32);
                #pragma unroll
                for (int ch = 0; ch < 8; ++ch) {
                    uint32_t nOff = (uint32_t)(((ch >> 1)*64 + (ch & 1)*16)*AROW_B + kt*32);
                    uint32_t bH[4], bL[4];
                    ldm4(bH, bBaseHi + nOff);
                    mma_bf16(acc[ch*2],   aH, bH[0], bH[1]);
                    mma_bf16(acc[ch*2+1], aH, bH[2], bH[3]);
                    mma_bf16(acc[ch*2],   aL, bH[0], bH[1]);
                    mma_bf16(acc[ch*2+1], aL, bH[2], bH[3]);
                    ldm4(bL, bBaseLo + nOff);
                    mma_bf16(acc[ch*2],   aH, bL[0], bL[1]);
                    mma_bf16(acc[ch*2+1], aH, bL[2], bL[3]);
                }
            }
        } else {
            __syncthreads();   // (c) still order pb4 write before epilogue read
        }
        // (d) epilogue
        float4 in0 = pb4[r0], in1 = pb4[r1];
        #pragma unroll
        for (int rw = 0; rw < 2; ++rw) {
            int row = rw ? r1 : r0;
            float4 in = rw ? in1 : in0;
            #pragma unroll
            for (int usub = 0; usub < 4; ++usub) {
                float hh[2];
                #pragma unroll
                for (int e = 0; e < 2; ++e) {
                    int u = nhalf*32 + usub*8 + 2*tig + e;
                    int di = rw*2 + e;
                    const float4* wu = WU + u*5;
                    float4 wi = wu[0], wf = wu[1], wg = wu[2], wo = wu[3], b4 = wu[4];
                    float ai = acc[usub][di]      + b4.x + in.x*wi.x + in.y*wi.y + in.z*wi.z + in.w*wi.w;
                    float af = acc[4+usub][di]    + b4.y + in.x*wf.x + in.y*wf.y + in.z*wf.z + in.w*wf.w;
                    float ag = acc[8+usub][di]    + b4.z + in.x*wg.x + in.y*wg.y + in.z*wg.z + in.w*wg.w;
                    float ao = acc[12+usub][di]   + b4.w + in.x*wo.x + in.y*wo.y + in.z*wo.z + in.w*wo.w;
                    int ci = rw*8 + usub*2 + e;
                    float c = sigf(af)*cst[ci] + sigf(ai)*tanhfast(ag);
                    cst[ci] = c;
                    float h = sigf(ao)*tanhfast(c);
                    hh[e] = h;
                    if (t == Tn-1) sm[HST_F + row*STRIDE_H + u] = h;
                }
                int ub = nhalf*32 + usub*8 + 2*tig;
                float h0hi = __bfloat162float(__float2bfloat16(hh[0]));
                float h1hi = __bfloat162float(__float2bfloat16(hh[1]));
                *(uint32_t*)(smc + row*AROW_B + ub*2)         = pkbf2(h0hi, h1hi);
                *(uint32_t*)(smc + 18432 + row*AROW_B + ub*2) = pkbf2(hh[0]-h0hi, hh[1]-h1hi);
            }
        }
        __syncthreads();   // (e)
    }

    // ---------------- MLPs (fma2 path) ----------------
    const int r = tid & 127;
    const int q = tid >> 7;
    const int u0m = q * 16;
    const int grow = blockIdx.x*128 + r;
    u64 h2[32];

    load_h2(h2, sm + HST_F + r*STRIDE_H);
    __syncthreads();
    if (q == 0) {   // stash hT in A region (free during MLP)
        float* stash = sm + AHI_F + r*64;
        const float* hsrc = sm + HST_F + r*STRIDE_H;
        #pragma unroll
        for (int k = 0; k < 64; k += 4) *(float4*)(stash + k) = *(const float4*)(hsrc + k);
    }
    __syncthreads();

    cpw(sm + BW_F,         mean_Ws, 12288);
    cpw(sm + BW_F + 12288, mean_Wf, 6400);
    cpw(sm + BW_F + 18688, mean_bs, 192);
    cpw(sm + BW_F + 18880, mean_bf, 100);
    __syncthreads();
    mlp_forward(sm + BW_F, h2, sm + HST_F + r*STRIDE_H, u0m, q,
                sm + ZB_F + r*STRIDE_Z, out + OFF_MU + (size_t)grow*100, false, nullptr);
    __syncthreads();

    load_h2(h2, sm + AHI_F + r*64);
    cpw(sm + BW_F,         lv_Ws, 12288);
    cpw(sm + BW_F + 12288, lv_Wf, 6400);
    cpw(sm + BW_F + 18688, lv_bs, 192);
    cpw(sm + BW_F + 18880, lv_bf, 100);
    __syncthreads();
    mlp_forward(sm + BW_F, h2, sm + HST_F + r*STRIDE_H, u0m, q,
                sm + ZB_F + r*STRIDE_Z, out + OFF_LV + (size_t)grow*100, true, eps + (size_t)grow*100);
    __syncthreads();

    // dh = z @ W_init^T + b_init -> HST
    cpw(sm + BW_F,        W_init, 6400);
    cpw(sm + BW_F + 6400, b_init, 64);
    __syncthreads();
    {
        const ulonglong2* z2 = (const ulonglong2*)(sm + ZB_F + r*STRIDE_Z);
        #pragma unroll 1
        for (int j = u0m; j < u0m+16; ++j) {
            const ulonglong2* w2 = (const ulonglong2*)(sm + BW_F + j*100);
            u64 A = 0ULL, B = 0ULL;
            #pragma unroll
            for (int i = 0; i < 25; ++i) {
                ulonglong2 w = w2[i], z = z2[i];
                A = fma2(z.x, w.x, A);
                B = fma2(z.y, w.y, B);
            }
            sm[HST_F + r*STRIDE_H + j] = hsum2(A) + hsum2(B) + sm[BW_F + 6400 + j];
        }
    }
    __syncthreads();

    // ---------------- decoder setup ----------------
    cpB(sm + BW_F,        g_Bhi_d);
    cpB(sm + BW_F + 9216, g_Blo_d);
    cpWU(sm + WFB_F, g_wfp_d, g_bfp_d);
    cpw(sm + WC_F, W_c, 128);
    if (tid == 0) { sm[WC_F+128] = b_c[0]; sm[WC_F+129] = b_c[1]; }
    if (tid < 128) pb4[tid] = ((const float4*)init_state)[blockIdx.x*128 + tid];
    __syncthreads();

    // c0 = h0 = dh; write A tiles from HST
    #pragma unroll
    for (int rw = 0; rw < 2; ++rw) {
        int row = rw ? r1 : r0;
        #pragma unroll
        for (int usub = 0; usub < 4; ++usub) {
            int ub = nhalf*32 + usub*8 + 2*tig;
            float h0 = sm[HST_F + row*STRIDE_H + ub];
            float h1 = sm[HST_F + row*STRIDE_H + ub + 1];
            cst[rw*8 + usub*2]     = h0;
            cst[rw*8 + usub*2 + 1] = h1;
            float h0hi = __bfloat162float(__float2bfloat16(h0));
            float h1hi = __bfloat162float(__float2bfloat16(h1));
            *(uint32_t*)(smc + row*AROW_B + ub*2)         = pkbf2(h0hi, h1hi);
            *(uint32_t*)(smc + 18432 + row*AROW_B + ub*2) = pkbf2(h0-h0hi, h1-h1hi);
        }
    }

    float4 prev;
    if (tid < 128) prev = pb4[tid];
    const float* wc0 = sm + WC_F;
    const float* wc1 = sm + WC_F + 64;
    float* rec = out + (size_t)(blockIdx.x*128 + tid)*(Tn*4);   // valid for tid<128

    // ---------------- decoder loop ----------------
    #pragma unroll 1
    for (int t = 0; t < Tn; ++t) {
        __syncthreads();   // (c): A tiles + pb4 ready
        float acc[16][4];
        #pragma unroll
        for (int i = 0; i < 16; ++i) { acc[i][0]=0.f; acc[i][1]=0.f; acc[i][2]=0.f; acc[i][3]=0.f; }
        #pragma unroll
        for (int kt = 0; kt < 4; ++kt) {
            uint32_t aH[4], aL[4];
            ldm4(aH, aAddrH + kt*32);
            ldm4(aL, aAddrL + kt*32);
            #pragma unroll
            for (int ch = 0; ch < 8; ++ch) {
                uint32_t nOff = (uint32_t)(((ch >> 1)*64 + (ch & 1)*16)*AROW_B + kt*32);
                uint32_t bH[4], bL[4];
                ldm4(bH, bBaseHi + nOff);
                mma_bf16(acc[ch*2],   aH, bH[0], bH[1]);
                mma_bf16(acc[ch*2+1], aH, bH[2], bH[3]);
                mma_bf16(acc[ch*2],   aL, bH[0], bH[1]);
                mma_bf16(acc[ch*2+1], aL, bH[2], bH[3]);
                ldm4(bL, bBaseLo + nOff);
                mma_bf16(acc[ch*2],   aH, bL[0], bL[1]);
                mma_bf16(acc[ch*2+1], aH, bL[2], bL[3]);
            }
        }
        // epilogue: gates -> h, W_c partials, new A tiles
        float4 in0 = pb4[r0], in1 = pb4[r1];
        float pa[4] = {0.f, 0.f, 0.f, 0.f};   // [rw*2 + {0,1}]
        #pragma unroll
        for (int rw = 0; rw < 2; ++rw) {
            int row = rw ? r1 : r0;
            float4 in = rw ? in1 : in0;
            #pragma unroll
            for (int usub = 0; usub < 4; ++usub) {
                float hh[2];
                #pragma unroll
                for (int e = 0; e < 2; ++e) {
                    int u = nhalf*32 + usub*8 + 2*tig + e;
                    int di = rw*2 + e;
                    const float4* wu = WU + u*5;
                    float4 wi = wu[0], wf = wu[1], wg = wu[2], wo = wu[3], b4 = wu[4];
                    float ai = acc[usub][di]    + b4.x + in.x*wi.x + in.y*wi.y + in.z*wi.z + in.w*wi.w;
                    float af = acc[4+usub][di]  + b4.y + in.x*wf.x + in.y*wf.y + in.z*wf.z + in.w*wf.w;
                    float ag = acc[8+usub][di]  + b4.z + in.x*wg.x + in.y*wg.y + in.z*wg.z + in.w*wg.w;
                    float ao = acc[12+usub][di] + b4.w + in.x*wo.x + in.y*wo.y + in.z*wo.z + in.w*wo.w;
                    int ci = rw*8 + usub*2 + e;
                    float c = sigf(af)*cst[ci] + sigf(ai)*tanhfast(ag);
                    cst[ci] = c;
                    float h = sigf(ao)*tanhfast(c);
                    hh[e] = h;
                    pa[rw*2+0] = fmaf(h, wc0[u], pa[rw*2+0]);
                    pa[rw*2+1] = fmaf(h, wc1[u], pa[rw*2+1]);
                }
                int ub = nhalf*32 + usub*8 + 2*tig;
                float h0hi = __bfloat162float(__float2bfloat16(hh[0]));
                float h1hi = __bfloat162float(__float2bfloat16(hh[1]));
                *(uint32_t*)(smc + row*AROW_B + ub*2)         = pkbf2(h0hi, h1hi);
                *(uint32_t*)(smc + 18432 + row*AROW_B + ub*2) = pkbf2(hh[0]-h0hi, hh[1]-h1hi);
            }
        }
        // reduce W_c partials over tig (lanes gid*4+tig)
        #pragma unroll
        for (int i = 0; i < 4; ++i) {
            pa[i] += __shfl_xor_sync(0xFFFFFFFFu, pa[i], 1);
            pa[i] += __shfl_xor_sync(0xFFFFFFFFu, pa[i], 2);
        }
        if (tig == 0) {
            part[r0*4 + nhalf*2 + 0] = pa[0];
            part[r0*4 + nhalf*2 + 1] = pa[1];
            part[r1*4 + nhalf*2 + 0] = pa[2];
            part[r1*4 + nhalf*2 + 1] = pa[3];
        }
        __syncthreads();   // (e)
        // (f) dynamics
        if (tid < 128) {
            float a0 = part[tid*4+0] + part[tid*4+2] + sm[WC_F+128];
            float a1 = part[tid*4+1] + part[tid*4+3] + sm[WC_F+129];
            float steer = fminf(fmaxf(a1, -0.5f), 0.5f);
            float x = prev.x, y = prev.y, psi = prev.z, v = prev.w;
            float v1 = fminf(fmaxf(fmaf(a0, DTC, v), 0.0f), 30.0f);
            float pd = fminf(fmaxf(v * __tanf(steer) * (1.0f/2.5f), -1.57f), 1.57f);
            float s, c; __sincosf(psi, &s, &c);
            float4 cur = make_float4(fmaf(v*c, DTC, x), fmaf(v*s, DTC, y), fmaf(pd, DTC, psi), v1);
            *(float4*)(rec + t*4) = cur;
            pb4[tid] = cur;
            prev = cur;
        }
    }
}

extern "C" void kernel_launch(void* const* d_in, const int* in_sizes, int n_in,
                              void* d_out, int out_size)
{
    const float* expert     = (const float*)d_in[0];
    const float* init_state = (const float*)d_in[1];
    const float* eps        = (const float*)d_in[2];
    const float* W_se       = (const float*)d_in[3];
    const float* b_se       = (const float*)d_in[4];
    const float* W_ih_e     = (const float*)d_in[5];
    const float* W_hh_e     = (const float*)d_in[6];
    const float* b_ih_e     = (const float*)d_in[7];
    const float* b_hh_e     = (const float*)d_in[8];
    const float* mean_Ws    = (const float*)d_in[9];
    const float* mean_bs    = (const float*)d_in[10];
    const float* mean_Wf    = (const float*)d_in[11];
    const float* mean_bf    = (const float*)d_in[12];
    const float* lv_Ws      = (const float*)d_in[13];
    const float* lv_bs      = (const float*)d_in[14];
    const float* lv_Wf      = (const float*)d_in[15];
    const float* lv_bf      = (const float*)d_in[16];
    const float* W_init     = (const float*)d_in[17];
    const float* b_init     = (const float*)d_in[18];
    const float* W_ih_d     = (const float*)d_in[19];
    const float* W_hh_d     = (const float*)d_in[20];
    const float* b_ih_d     = (const float*)d_in[21];
    const float* b_hh_d     = (const float*)d_in[22];
    const float* W_c        = (const float*)d_in[23];
    const float* b_c        = (const float*)d_in[24];
    float* out = (float*)d_out;

    cudaFuncSetAttribute(vae_kernel, cudaFuncAttributeMaxDynamicSharedMemorySize, SMEM_BYTES);

    prep_kernel<<<64, 256>>>(W_se, b_se, W_ih_e, W_hh_e, b_ih_e, b_hh_e,
                             W_ih_d, W_hh_d, b_ih_d, b_hh_d);
    copy_kernel<<<256, 256>>>((const float4*)expert, (float4*)(out + OFF_EXP), N_REC/4);
    vae_kernel<<<NB, NT, SMEM_BYTES>>>(expert, init_state, eps,
        mean_Ws, mean_bs, mean_Wf, mean_bf,
        lv_Ws, lv_bs, lv_Wf, lv_bf,
        W_init, b_init, W_c, b_c, out);
}